// round 3
// baseline (speedup 1.0000x reference)
#include <cuda_runtime.h>
#include <cuda_bf16.h>
#include <math.h>

// ---------------------------------------------------------------------------
// SpatialTransformerInputHead  (B=128, H=W=256, C=1)
//   conv1 5x5 1->14 VALID + relu + maxpool2   -> [128,126,126,14]
//   conv2 5x5 14->32 VALID + relu + maxpool2  -> [128,61,61,32]
//   dense 119072->120 relu, 120->84 relu, 84->6 -> theta [128,2,3]
//   bilinear grid sample of input + 1x1 conv + sigmoid -> [128,256,256,1]
// ---------------------------------------------------------------------------

typedef unsigned long long ull;

#define BATCH 128
#define HW    256
#define P1    126          // pooled conv1 spatial
#define P2    61           // pooled conv2 spatial
#define FLAT  (61*61*32)   // 119072
#define KSPLITS 64
#define KCHUNK  1861       // ceil(119072/64)

// --------- scratch (device globals; no allocation APIs allowed) ------------
__device__ float g_buf1[(size_t)BATCH*14*P1*P1];      // conv1 pooled, NCHW
__device__ float g_buf2[(size_t)BATCH*FLAT];          // conv2 pooled, NHWC flat
__device__ float g_part[(size_t)KSPLITS*BATCH*120];   // dense1 split-K partials
__device__ float g_theta[BATCH*6];

// --------- packed f32x2 helpers --------------------------------------------
__device__ __forceinline__ ull pk2(float v) {
    ull r;
    asm("mov.b64 %0, {%1, %2};" : "=l"(r) : "f"(v), "f"(v));
    return r;
}
__device__ __forceinline__ void upk2(ull v, float& lo, float& hi) {
    asm("mov.b64 {%0, %1}, %2;" : "=f"(lo), "=f"(hi) : "l"(v));
}
#define FMA2(d, a, b) asm("fma.rn.f32x2 %0, %1, %2, %0;" : "+l"(d) : "l"(a), "l"(b))

// ===========================================================================
// conv1 (5x5, 1->14) + relu + maxpool2.  Block: 16x16 pooled tile, 1 image.
// grid (8,8,128), 256 threads.  Output NCHW [B][14][126][126].
// ===========================================================================
__global__ void __launch_bounds__(256) conv1_kernel(
    const float* __restrict__ x, const float* __restrict__ w,
    const float* __restrict__ bias)
{
    __shared__ __align__(16) float sw[352];       // 350 used; aligned for LDS.64
    __shared__ __align__(16) float sb[16];
    __shared__ __align__(16) float sin_[36*36];

    const int b  = blockIdx.z;
    const int ox = blockIdx.x * 32;     // conv-space / input-space origin
    const int oy = blockIdx.y * 32;
    const int tid = threadIdx.x;

    for (int i = tid; i < 350; i += 256) sw[i] = w[i];   // FIX: strided (350 > 256)
    if (tid < 14)  sb[tid] = bias[tid];

    const float* xb = x + (size_t)b * (HW*HW);
    for (int i = tid; i < 36*36; i += 256) {
        int r = i / 36, c = i % 36;
        int gy = oy + r, gx = ox + c;
        sin_[i] = (gy < HW && gx < HW) ? xb[gy*HW + gx] : 0.f;
    }
    __syncthreads();

    const int tx = tid & 15, ty = tid >> 4;

    ull acc[4][7];
#pragma unroll
    for (int p = 0; p < 4; ++p)
#pragma unroll
        for (int j = 0; j < 7; ++j) acc[p][j] = 0ull;

    const float* ib = sin_ + (2*ty)*36 + 2*tx;
#pragma unroll
    for (int dy = 0; dy < 5; ++dy) {
        const float* ra = ib + dy*36;
        const float* rb = ra + 36;
#pragma unroll
        for (int dx = 0; dx < 5; ++dx) {
            ull p00 = pk2(ra[dx]);
            ull p01 = pk2(ra[dx+1]);
            ull p10 = pk2(rb[dx]);
            ull p11 = pk2(rb[dx+1]);
            const ull* wp = (const ull*)&sw[(dy*5 + dx)*14];
#pragma unroll
            for (int j = 0; j < 7; ++j) {
                ull wv = wp[j];
                FMA2(acc[0][j], p00, wv);
                FMA2(acc[1][j], p01, wv);
                FMA2(acc[2][j], p10, wv);
                FMA2(acc[3][j], p11, wv);
            }
        }
    }

    const int x0 = blockIdx.x*16 + tx;
    const int y0 = blockIdx.y*16 + ty;
    if (x0 < P1 && y0 < P1) {
        float* ob = g_buf1 + (size_t)b*14*P1*P1 + (size_t)y0*P1 + x0;
#pragma unroll
        for (int j = 0; j < 7; ++j) {
            float l0,h0,l1,h1,l2,h2,l3,h3;
            upk2(acc[0][j], l0, h0);
            upk2(acc[1][j], l1, h1);
            upk2(acc[2][j], l2, h2);
            upk2(acc[3][j], l3, h3);
            float m0 = fmaxf(fmaxf(l0,l1), fmaxf(l2,l3)) + sb[2*j];
            float m1 = fmaxf(fmaxf(h0,h1), fmaxf(h2,h3)) + sb[2*j+1];
            ob[(size_t)(2*j)  *P1*P1] = fmaxf(m0, 0.f);
            ob[(size_t)(2*j+1)*P1*P1] = fmaxf(m1, 0.f);
        }
    }
}

// ===========================================================================
// conv2 (5x5, 14->32) + relu + maxpool2.  Block: 16x16 pooled tile, 1 image.
// grid (4,4,128), 256 threads, 117.5 KB dynamic smem.
// Output NHWC-flat [B][61*61*32] (matches reshape(B,-1) flatten order).
// ===========================================================================
#define C2_SMEM_FLOATS (11200 + 32 + 14*36*36)   // 29376 floats = 117504 B

__global__ void __launch_bounds__(256) conv2_kernel(
    const float* __restrict__ w, const float* __restrict__ bias)
{
    extern __shared__ __align__(16) float smem[];
    float* sw   = smem;             // [5][5][14][32]
    float* sb   = smem + 11200;     // [32]
    float* sin_ = smem + 11232;     // [14][36][36]

    const int b  = blockIdx.z;
    const int ox = blockIdx.x * 32;
    const int oy = blockIdx.y * 32;
    const int tid = threadIdx.x;

    for (int i = tid; i < 11200; i += 256) sw[i] = w[i];
    if (tid < 32) sb[tid] = bias[tid];

    for (int i = tid; i < 14*36*36; i += 256) {
        int ci  = i / 1296;
        int rem = i - ci*1296;
        int r = rem / 36, c = rem % 36;
        int gy = oy + r, gx = ox + c;
        sin_[i] = (gy < P1 && gx < P1)
                ? g_buf1[((size_t)(b*14 + ci)*P1 + gy)*P1 + gx] : 0.f;
    }
    __syncthreads();

    const int tx = tid & 15, ty = tid >> 4;
    const int x0 = blockIdx.x*16 + tx;
    const int y0 = blockIdx.y*16 + ty;

#pragma unroll 1
    for (int half = 0; half < 2; ++half) {
        ull acc[4][8];
#pragma unroll
        for (int p = 0; p < 4; ++p)
#pragma unroll
            for (int j = 0; j < 8; ++j) acc[p][j] = 0ull;

#pragma unroll 1
        for (int ci = 0; ci < 14; ++ci) {
            const float* ib = sin_ + ci*1296 + (2*ty)*36 + 2*tx;
#pragma unroll
            for (int dy = 0; dy < 5; ++dy) {
                const float* ra = ib + dy*36;
                const float* rb = ra + 36;
#pragma unroll
                for (int dx = 0; dx < 5; ++dx) {
                    ull p00 = pk2(ra[dx]);
                    ull p01 = pk2(ra[dx+1]);
                    ull p10 = pk2(rb[dx]);
                    ull p11 = pk2(rb[dx+1]);
                    const ull* wp = (const ull*)&sw[((dy*5 + dx)*14 + ci)*32 + half*16];
#pragma unroll
                    for (int j = 0; j < 8; ++j) {
                        ull wv = wp[j];
                        FMA2(acc[0][j], p00, wv);
                        FMA2(acc[1][j], p01, wv);
                        FMA2(acc[2][j], p10, wv);
                        FMA2(acc[3][j], p11, wv);
                    }
                }
            }
        }

        if (x0 < P2 && y0 < P2) {
            float* ob = g_buf2 + (((size_t)b*P2 + y0)*P2 + x0)*32 + half*16;
#pragma unroll
            for (int j = 0; j < 8; ++j) {
                float l0,h0,l1,h1,l2,h2,l3,h3;
                upk2(acc[0][j], l0, h0);
                upk2(acc[1][j], l1, h1);
                upk2(acc[2][j], l2, h2);
                upk2(acc[3][j], l3, h3);
                float m0 = fmaxf(fmaxf(l0,l1), fmaxf(l2,l3)) + sb[half*16 + 2*j];
                float m1 = fmaxf(fmaxf(h0,h1), fmaxf(h2,h3)) + sb[half*16 + 2*j+1];
                ob[2*j]   = fmaxf(m0, 0.f);
                ob[2*j+1] = fmaxf(m1, 0.f);
            }
        }
    }
}

// ===========================================================================
// dense1 split-K GEMM:  [128 x 119072] @ [119072 x 120] -> partials.
// grid (5, 64): 24 output cols per x-block, K chunk of 1861 per y-block.
// Deterministic (no atomics): partials reduced in dense23_kernel.
// ===========================================================================
__global__ void __launch_bounds__(256) dense1_kernel(const float* __restrict__ w)
{
    __shared__ __align__(16) float As[32*129];
    __shared__ __align__(16) float Ws[32*24];

    const int o0   = blockIdx.x * 24;
    const int k0   = blockIdx.y * KCHUNK;
    const int kend = min(k0 + KCHUNK, FLAT);
    const int tid  = threadIdx.x;
    const int bb   = tid & 127;
    const int g    = tid >> 7;          // 0/1 -> 12 output cols each

    float acc[12];
#pragma unroll
    for (int j = 0; j < 12; ++j) acc[j] = 0.f;

    for (int kb = k0; kb < kend; kb += 32) {
        for (int i = tid; i < 128*32; i += 256) {
            int r  = i >> 5;
            int kk = i & 31;
            int k  = kb + kk;
            As[kk*129 + r] = (k < kend) ? g_buf2[(size_t)r*FLAT + k] : 0.f;
        }
        for (int i = tid; i < 32*24; i += 256) {
            int kk = i / 24, oo = i - kk*24;
            int k = kb + kk;
            Ws[i] = (k < kend) ? w[(size_t)k*120 + o0 + oo] : 0.f;
        }
        __syncthreads();
#pragma unroll
        for (int kk = 0; kk < 32; ++kk) {
            float a = As[kk*129 + bb];
#pragma unroll
            for (int j = 0; j < 12; ++j)
                acc[j] = fmaf(a, Ws[kk*24 + g*12 + j], acc[j]);
        }
        __syncthreads();
    }

    float* p = g_part + ((size_t)blockIdx.y*BATCH + bb)*120 + o0 + g*12;
#pragma unroll
    for (int j = 0; j < 12; ++j) p[j] = acc[j];
}

// ===========================================================================
// dense23: reduce split-K partials + bias + relu -> h1[120];
//          h2 = relu(h1 @ d2_w + b2);  theta = h2 @ d3_w + b3.
// grid 128 (one block per batch row), 128 threads.
// ===========================================================================
__global__ void __launch_bounds__(128) dense23_kernel(
    const float* __restrict__ d1b,
    const float* __restrict__ d2w, const float* __restrict__ d2b,
    const float* __restrict__ d3w, const float* __restrict__ d3b)
{
    __shared__ float h1[120];
    __shared__ float h2[84];
    const int b = blockIdx.x, t = threadIdx.x;

    if (t < 120) {
        float s = d1b[t];
        for (int i = 0; i < KSPLITS; ++i)
            s += g_part[((size_t)i*BATCH + b)*120 + t];
        h1[t] = fmaxf(s, 0.f);
    }
    __syncthreads();
    if (t < 84) {
        float s = d2b[t];
#pragma unroll 4
        for (int k = 0; k < 120; ++k)
            s = fmaf(h1[k], d2w[k*84 + t], s);
        h2[t] = fmaxf(s, 0.f);
    }
    __syncthreads();
    if (t < 6) {
        float s = d3b[t];
#pragma unroll 4
        for (int k = 0; k < 84; ++k)
            s = fmaf(h2[k], d3w[k*6 + t], s);
        g_theta[b*6 + t] = s;
    }
}

// ===========================================================================
// sampler: affine grid + bilinear sample (clipped-neighbor weights, matching
// the reference exactly) + 1x1 conv + sigmoid.
// grid (256 rows, 128 batch), 256 threads (columns).
// ===========================================================================
__global__ void __launch_bounds__(256) sampler_kernel(
    const float* __restrict__ x, const float* __restrict__ ow,
    const float* __restrict__ ob, float* __restrict__ out)
{
    __shared__ float th[6];
    const int b = blockIdx.y;
    const int h = blockIdx.x;
    const int w = threadIdx.x;
    if (w < 6) th[w] = g_theta[b*6 + w];
    __syncthreads();

    const float gx = (float)w * (2.f/256.f) - 1.f;
    const float gy = (float)h * (2.f/256.f) - 1.f;
    const float px = (th[0]*gx + th[1]*gy + th[2] + 1.f) * 128.f;
    const float py = (th[3]*gx + th[4]*gy + th[5] + 1.f) * 128.f;

    const int fx = (int)floorf(px);
    const int fy = (int)floorf(py);
    const int x1 = min(max(fx,     0), HW-1);
    const int x2 = min(max(fx + 1, 0), HW-1);
    const int y1 = min(max(fy,     0), HW-1);
    const int y2 = min(max(fy + 1, 0), HW-1);

    const float* img = x + (size_t)b * (HW*HW);
    const float p11 = img[y1*HW + x1];
    const float p12 = img[y2*HW + x1];
    const float p21 = img[y1*HW + x2];
    const float p22 = img[y2*HW + x2];

    const float wx1 = (float)x2 - px;
    const float wx2 = px - (float)x1;
    const float wy1 = (float)y2 - py;
    const float wy2 = py - (float)y1;

    const float r = wx1*(wy1*p11 + wy2*p12) + wx2*(wy1*p21 + wy2*p22);
    const float t = r * __ldg(ow) + __ldg(ob);
    out[((size_t)b*HW + h)*HW + w] = 1.f / (1.f + expf(-t));
}

// ===========================================================================
// launch
// ===========================================================================
extern "C" void kernel_launch(void* const* d_in, const int* in_sizes, int n_in,
                              void* d_out, int out_size)
{
    const float* x      = (const float*)d_in[0];
    const float* c1w    = (const float*)d_in[1];
    const float* c1b    = (const float*)d_in[2];
    const float* c2w    = (const float*)d_in[3];
    const float* c2b    = (const float*)d_in[4];
    const float* d1w    = (const float*)d_in[5];
    const float* d1b    = (const float*)d_in[6];
    const float* d2w    = (const float*)d_in[7];
    const float* d2b    = (const float*)d_in[8];
    const float* d3w    = (const float*)d_in[9];
    const float* d3b    = (const float*)d_in[10];
    const float* outw   = (const float*)d_in[11];
    const float* outb   = (const float*)d_in[12];
    float* out = (float*)d_out;

    (void)in_sizes; (void)n_in; (void)out_size;

    // idempotent; host-side, not a stream op (graph-capture safe)
    cudaFuncSetAttribute(conv2_kernel,
                         cudaFuncAttributeMaxDynamicSharedMemorySize,
                         C2_SMEM_FLOATS * (int)sizeof(float));

    conv1_kernel<<<dim3(8, 8, BATCH), 256>>>(x, c1w, c1b);
    conv2_kernel<<<dim3(4, 4, BATCH), 256,
                   C2_SMEM_FLOATS * sizeof(float)>>>(c2w, c2b);
    dense1_kernel<<<dim3(5, KSPLITS), 256>>>(d1w);
    dense23_kernel<<<BATCH, 128>>>(d1b, d2w, d2b, d3w, d3b);
    sampler_kernel<<<dim3(HW, BATCH), 256>>>(x, outw, outb, out);
}

// round 4
// speedup vs baseline: 2.0329x; 2.0329x over previous
#include <cuda_runtime.h>
#include <cuda_bf16.h>
#include <math.h>

// ---------------------------------------------------------------------------
// SpatialTransformerInputHead  (B=128, H=W=256, C=1)
//   conv1 5x5 1->14 VALID + relu + maxpool2   -> [128,126,126,16(pad)] bf16
//   conv2 5x5 14->32 VALID + relu + maxpool2  -> [128,61,61,32] bf16   (HMMA)
//   dense 119072->120 relu, 120->84 relu, 84->6 -> theta [128,2,3]
//   bilinear grid sample of input + 1x1 conv + sigmoid -> [128,256,256,1]
// ---------------------------------------------------------------------------

typedef unsigned long long ull;
typedef unsigned int uint32;

#define BATCH 128
#define HW    256
#define P1    126          // conv1 pooled spatial
#define P2    61           // conv2 pooled spatial
#define FLAT  (61*61*32)   // 119072
#define KSPLITS 64
#define KCHUNK  1861       // ceil(119072/64)

// --------- scratch (device globals; no allocation APIs allowed) ------------
__device__ __nv_bfloat16 g_buf1[(size_t)BATCH*P1*P1*16];   // conv1 pooled, NHWC ch-pad 16
__device__ __nv_bfloat16 g_buf2[(size_t)BATCH*FLAT];       // conv2 pooled, NHWC flat
__device__ float g_part[(size_t)KSPLITS*BATCH*120];        // dense1 split-K partials
__device__ float g_theta[BATCH*6];

// --------- packed f32x2 helpers --------------------------------------------
__device__ __forceinline__ ull pk2(float v) {
    ull r;
    asm("mov.b64 %0, {%1, %2};" : "=l"(r) : "f"(v), "f"(v));
    return r;
}
__device__ __forceinline__ void upk2(ull v, float& lo, float& hi) {
    asm("mov.b64 {%0, %1}, %2;" : "=f"(lo), "=f"(hi) : "l"(v));
}
#define FMA2(d, a, b) asm("fma.rn.f32x2 %0, %1, %2, %0;" : "+l"(d) : "l"(a), "l"(b))

__device__ __forceinline__ uint32 smem_u32(const void* p) {
    uint32 a;
    asm("{ .reg .u64 t; cvta.to.shared.u64 t, %1; cvt.u32.u64 %0, t; }"
        : "=r"(a) : "l"(p));
    return a;
}

// ===========================================================================
// conv1 (5x5, 1->14) + relu + maxpool2, fp32 f32x2 math, bf16 NHWC16 output.
// grid (8,8,128), 256 threads.
// ===========================================================================
__global__ void __launch_bounds__(256) conv1_kernel(
    const float* __restrict__ x, const float* __restrict__ w,
    const float* __restrict__ bias)
{
    __shared__ __align__(16) float sw[352];
    __shared__ __align__(16) float sb[16];
    __shared__ __align__(16) float sin_[36*36];

    const int b  = blockIdx.z;
    const int ox = blockIdx.x * 32;
    const int oy = blockIdx.y * 32;
    const int tid = threadIdx.x;

    for (int i = tid; i < 350; i += 256) sw[i] = w[i];
    if (tid < 14)  sb[tid] = bias[tid];

    const float* xb = x + (size_t)b * (HW*HW);
    for (int i = tid; i < 36*36; i += 256) {
        int r = i / 36, c = i % 36;
        int gy = oy + r, gx = ox + c;
        sin_[i] = (gy < HW && gx < HW) ? xb[gy*HW + gx] : 0.f;
    }
    __syncthreads();

    const int tx = tid & 15, ty = tid >> 4;

    ull acc[4][7];
#pragma unroll
    for (int p = 0; p < 4; ++p)
#pragma unroll
        for (int j = 0; j < 7; ++j) acc[p][j] = 0ull;

    const float* ib = sin_ + (2*ty)*36 + 2*tx;
#pragma unroll
    for (int dy = 0; dy < 5; ++dy) {
        const float* ra = ib + dy*36;
        const float* rb = ra + 36;
#pragma unroll
        for (int dx = 0; dx < 5; ++dx) {
            ull p00 = pk2(ra[dx]);
            ull p01 = pk2(ra[dx+1]);
            ull p10 = pk2(rb[dx]);
            ull p11 = pk2(rb[dx+1]);
            const ull* wp = (const ull*)&sw[(dy*5 + dx)*14];
#pragma unroll
            for (int j = 0; j < 7; ++j) {
                ull wv = wp[j];
                FMA2(acc[0][j], p00, wv);
                FMA2(acc[1][j], p01, wv);
                FMA2(acc[2][j], p10, wv);
                FMA2(acc[3][j], p11, wv);
            }
        }
    }

    const int x0 = blockIdx.x*16 + tx;
    const int y0 = blockIdx.y*16 + ty;
    if (x0 < P1 && y0 < P1) {
        union { uint4 u[2]; __nv_bfloat16 h[16]; } pk;
#pragma unroll
        for (int j = 0; j < 7; ++j) {
            float l0,h0,l1,h1,l2,h2,l3,h3;
            upk2(acc[0][j], l0, h0);
            upk2(acc[1][j], l1, h1);
            upk2(acc[2][j], l2, h2);
            upk2(acc[3][j], l3, h3);
            float m0 = fmaxf(fmaxf(l0,l1), fmaxf(l2,l3)) + sb[2*j];
            float m1 = fmaxf(fmaxf(h0,h1), fmaxf(h2,h3)) + sb[2*j+1];
            pk.h[2*j]   = __float2bfloat16(fmaxf(m0, 0.f));
            pk.h[2*j+1] = __float2bfloat16(fmaxf(m1, 0.f));
        }
        pk.h[14] = __float2bfloat16(0.f);
        pk.h[15] = __float2bfloat16(0.f);
        uint4* dst = (uint4*)(g_buf1 + ((size_t)(b*P1 + y0)*P1 + x0)*16);
        dst[0] = pk.u[0];
        dst[1] = pk.u[1];
    }
}

// ===========================================================================
// conv2 via bf16 HMMA (mma.sync.m16n8k16): 5x5 conv = 25 shifted 1x1 GEMMs,
// K = 16 padded channels per tap.  Block: 16x16 pooled = 32x32 conv positions,
// 512 threads (16 warps), each warp: 2 conv rows x 32 cols (M=64) x N=32.
// Epilogue: 2x2 maxpool + bias + relu -> bf16 NHWC flat g_buf2.
// ===========================================================================
#define C2_TILE_B   41472            // 36*36 positions * 32 B
#define C2_W_B      25600            // 25*32*16 bf16
#define C2_SMEM_B   (C2_TILE_B + C2_W_B + 128)

__global__ void __launch_bounds__(512) conv2_kernel(
    const float* __restrict__ w, const float* __restrict__ bias)
{
    extern __shared__ __align__(16) unsigned char smem_raw[];
    __nv_bfloat16* tile = (__nv_bfloat16*)smem_raw;              // [36][36][16]
    __nv_bfloat16* Wsm  = (__nv_bfloat16*)(smem_raw + C2_TILE_B); // [25][32 co][16 ci]
    float* sb           = (float*)(smem_raw + C2_TILE_B + C2_W_B);

    const int b   = blockIdx.z;
    const int px0 = blockIdx.x * 16;   // pooled origin
    const int py0 = blockIdx.y * 16;
    const int ix0 = px0 * 2;           // conv/input origin
    const int iy0 = py0 * 2;
    const int tid = threadIdx.x;

    // weights: HWIO fp32 [tap][ci(14)][co(32)] -> bf16 [tap][co][ci(16 pad)]
    for (int i = tid; i < 12800; i += 512) {
        int tap = i >> 9;
        int co  = (i >> 4) & 31;
        int ci  = i & 15;
        float v = (ci < 14) ? w[tap*448 + ci*32 + co] : 0.f;
        Wsm[i] = __float2bfloat16(v);
    }
    if (tid < 32) sb[tid] = bias[tid];

    // input tile: 36x36 positions x 16 ch (32 B each)
    for (int p = tid; p < 1296; p += 512) {
        int r = p / 36, c = p % 36;
        int gy = iy0 + r, gx = ix0 + c;
        uint4 v0 = make_uint4(0,0,0,0), v1 = make_uint4(0,0,0,0);
        if (gy < P1 && gx < P1) {
            const uint4* src = (const uint4*)(g_buf1 + ((size_t)(b*P1 + gy)*P1 + gx)*16);
            v0 = src[0]; v1 = src[1];
        }
        uint4* dst = (uint4*)(tile + (size_t)p*16);
        dst[0] = v0; dst[1] = v1;
    }
    __syncthreads();

    const int warp = tid >> 5, lane = tid & 31;
    const int y0 = 2 * warp;                  // conv rows y0, y0+1

    // ldmatrix per-lane base addresses for the 4 (s, xh) m-tiles
    const uint32 tbase = smem_u32(tile);
    const int lrow = lane & 15, lhalf = lane >> 4;
    uint32 a_addr[2][2];
#pragma unroll
    for (int s = 0; s < 2; ++s)
#pragma unroll
        for (int xh = 0; xh < 2; ++xh)
            a_addr[s][xh] = tbase + (uint32)((y0 + s)*1152 + (xh*16 + lrow)*32 + lhalf*16);

    float cacc[2][2][4][4];
#pragma unroll
    for (int s = 0; s < 2; ++s)
#pragma unroll
        for (int xh = 0; xh < 2; ++xh)
#pragma unroll
            for (int nf = 0; nf < 4; ++nf)
#pragma unroll
                for (int k = 0; k < 4; ++k) cacc[s][xh][nf][k] = 0.f;

    const int nlocal = lane >> 2, k2 = (lane & 3) * 2;

#pragma unroll 1
    for (int tap = 0; tap < 25; ++tap) {
        const int dy = tap / 5, dx = tap % 5;
        const uint32 toff = (uint32)(dy*1152 + dx*32);

        // B fragments (col-major K x N): b0={k,k+1 @ n}, b1={k+8,k+9 @ n}
        uint32 bf[4][2];
        const __nv_bfloat16* wt = Wsm + tap*512;
#pragma unroll
        for (int nf = 0; nf < 4; ++nf) {
            const __nv_bfloat16* wn = wt + (nf*8 + nlocal)*16 + k2;
            bf[nf][0] = *(const uint32*)(wn);
            bf[nf][1] = *(const uint32*)(wn + 8);
        }

#pragma unroll
        for (int s = 0; s < 2; ++s)
#pragma unroll
        for (int xh = 0; xh < 2; ++xh) {
            uint32 a0, a1, a2, a3;
            asm volatile(
                "ldmatrix.sync.aligned.m8n8.x4.shared.b16 {%0,%1,%2,%3}, [%4];"
                : "=r"(a0), "=r"(a1), "=r"(a2), "=r"(a3)
                : "r"(a_addr[s][xh] + toff));
#pragma unroll
            for (int nf = 0; nf < 4; ++nf) {
                asm volatile(
                    "mma.sync.aligned.m16n8k16.row.col.f32.bf16.bf16.f32 "
                    "{%0,%1,%2,%3}, {%4,%5,%6,%7}, {%8,%9}, {%0,%1,%2,%3};"
                    : "+f"(cacc[s][xh][nf][0]), "+f"(cacc[s][xh][nf][1]),
                      "+f"(cacc[s][xh][nf][2]), "+f"(cacc[s][xh][nf][3])
                    : "r"(a0), "r"(a1), "r"(a2), "r"(a3),
                      "r"(bf[nf][0]), "r"(bf[nf][1]));
            }
        }
    }

    // epilogue: maxpool 2x2 (y across s, x across frag-row pairs) + bias + relu
    const int py = py0 + warp;
    const int r  = lane >> 2;               // c-frag row (0..7)
    const bool active = ((r & 1) == 0);
    const int j = r >> 1;                    // pooled x sub-index (0..3)
    const int n0 = (lane & 3) * 2;           // channel pair base within n-frag

#pragma unroll
    for (int xh = 0; xh < 2; ++xh)
#pragma unroll
    for (int nf = 0; nf < 4; ++nf) {
        float m0 = fmaxf(cacc[0][xh][nf][0], cacc[1][xh][nf][0]);  // (r,   n0)
        float m1 = fmaxf(cacc[0][xh][nf][1], cacc[1][xh][nf][1]);  // (r,   n0+1)
        float m2 = fmaxf(cacc[0][xh][nf][2], cacc[1][xh][nf][2]);  // (r+8, n0)
        float m3 = fmaxf(cacc[0][xh][nf][3], cacc[1][xh][nf][3]);  // (r+8, n0+1)
        float o0 = fmaxf(m0, __shfl_down_sync(0xffffffffu, m0, 4));
        float o1 = fmaxf(m1, __shfl_down_sync(0xffffffffu, m1, 4));
        float o2 = fmaxf(m2, __shfl_down_sync(0xffffffffu, m2, 4));
        float o3 = fmaxf(m3, __shfl_down_sync(0xffffffffu, m3, 4));
        if (active && py < P2) {
            const int ch  = nf*8 + n0;
            const float b0v = sb[ch], b1v = sb[ch+1];
            const int pxa = px0 + xh*8 + j;
            const int pxb = pxa + 4;
            if (pxa < P2) {
                __nv_bfloat162 v = __floats2bfloat162_rn(
                    fmaxf(o0 + b0v, 0.f), fmaxf(o1 + b1v, 0.f));
                *(__nv_bfloat162*)(g_buf2 + (((size_t)b*P2 + py)*P2 + pxa)*32 + ch) = v;
            }
            if (pxb < P2) {
                __nv_bfloat162 v = __floats2bfloat162_rn(
                    fmaxf(o2 + b0v, 0.f), fmaxf(o3 + b1v, 0.f));
                *(__nv_bfloat162*)(g_buf2 + (((size_t)b*P2 + py)*P2 + pxb)*32 + ch) = v;
            }
        }
    }
}

// ===========================================================================
// dense1 split-K GEMM:  [128 x 119072](bf16) @ [119072 x 120] -> partials.
// grid (5, 64); f32x2-packed inner loop.
// ===========================================================================
__global__ void __launch_bounds__(256) dense1_kernel(const float* __restrict__ w)
{
    __shared__ __align__(16) float As[32*129];
    __shared__ __align__(16) float Ws[32*24];

    const int o0   = blockIdx.x * 24;
    const int k0   = blockIdx.y * KCHUNK;
    const int kend = min(k0 + KCHUNK, FLAT);
    const int tid  = threadIdx.x;
    const int bb   = tid & 127;
    const int g    = tid >> 7;

    ull acc[6];
#pragma unroll
    for (int j = 0; j < 6; ++j) acc[j] = 0ull;

    for (int kb = k0; kb < kend; kb += 32) {
        for (int i = tid; i < 128*32; i += 256) {
            int r  = i >> 5;
            int kk = i & 31;
            int k  = kb + kk;
            As[kk*129 + r] = (k < kend)
                ? __bfloat162float(g_buf2[(size_t)r*FLAT + k]) : 0.f;
        }
        for (int i = tid; i < 32*24; i += 256) {
            int kk = i / 24, oo = i - kk*24;
            int k = kb + kk;
            Ws[i] = (k < kend) ? w[(size_t)k*120 + o0 + oo] : 0.f;
        }
        __syncthreads();
#pragma unroll
        for (int kk = 0; kk < 32; ++kk) {
            ull a2 = pk2(As[kk*129 + bb]);
            const ull* wsp = (const ull*)&Ws[kk*24 + g*12];
#pragma unroll
            for (int j = 0; j < 6; ++j)
                FMA2(acc[j], a2, wsp[j]);
        }
        __syncthreads();
    }

    float* p = g_part + ((size_t)blockIdx.y*BATCH + bb)*120 + o0 + g*12;
#pragma unroll
    for (int j = 0; j < 6; ++j) {
        float lo, hi;
        upk2(acc[j], lo, hi);
        p[2*j]   = lo;
        p[2*j+1] = hi;
    }
}

// ===========================================================================
// dense23: reduce split-K partials + bias + relu -> h1[120];
//          h2 = relu(h1 @ d2_w + b2);  theta = h2 @ d3_w + b3.
// ===========================================================================
__global__ void __launch_bounds__(128) dense23_kernel(
    const float* __restrict__ d1b,
    const float* __restrict__ d2w, const float* __restrict__ d2b,
    const float* __restrict__ d3w, const float* __restrict__ d3b)
{
    __shared__ float h1[120];
    __shared__ float h2[84];
    const int b = blockIdx.x, t = threadIdx.x;

    if (t < 120) {
        float s = d1b[t];
        for (int i = 0; i < KSPLITS; ++i)
            s += g_part[((size_t)i*BATCH + b)*120 + t];
        h1[t] = fmaxf(s, 0.f);
    }
    __syncthreads();
    if (t < 84) {
        float s = d2b[t];
#pragma unroll 4
        for (int k = 0; k < 120; ++k)
            s = fmaf(h1[k], d2w[k*84 + t], s);
        h2[t] = fmaxf(s, 0.f);
    }
    __syncthreads();
    if (t < 6) {
        float s = d3b[t];
#pragma unroll 4
        for (int k = 0; k < 84; ++k)
            s = fmaf(h2[k], d3w[k*6 + t], s);
        g_theta[b*6 + t] = s;
    }
}

// ===========================================================================
// sampler: affine grid + bilinear sample + 1x1 conv + sigmoid.
// ===========================================================================
__global__ void __launch_bounds__(256) sampler_kernel(
    const float* __restrict__ x, const float* __restrict__ ow,
    const float* __restrict__ ob, float* __restrict__ out)
{
    __shared__ float th[6];
    const int b = blockIdx.y;
    const int h = blockIdx.x;
    const int w = threadIdx.x;
    if (w < 6) th[w] = g_theta[b*6 + w];
    __syncthreads();

    const float gx = (float)w * (2.f/256.f) - 1.f;
    const float gy = (float)h * (2.f/256.f) - 1.f;
    const float px = (th[0]*gx + th[1]*gy + th[2] + 1.f) * 128.f;
    const float py = (th[3]*gx + th[4]*gy + th[5] + 1.f) * 128.f;

    const int fx = (int)floorf(px);
    const int fy = (int)floorf(py);
    const int x1 = min(max(fx,     0), HW-1);
    const int x2 = min(max(fx + 1, 0), HW-1);
    const int y1 = min(max(fy,     0), HW-1);
    const int y2 = min(max(fy + 1, 0), HW-1);

    const float* img = x + (size_t)b * (HW*HW);
    const float p11 = img[y1*HW + x1];
    const float p12 = img[y2*HW + x1];
    const float p21 = img[y1*HW + x2];
    const float p22 = img[y2*HW + x2];

    const float wx1 = (float)x2 - px;
    const float wx2 = px - (float)x1;
    const float wy1 = (float)y2 - py;
    const float wy2 = py - (float)y1;

    const float r = wx1*(wy1*p11 + wy2*p12) + wx2*(wy1*p21 + wy2*p22);
    const float t = r * __ldg(ow) + __ldg(ob);
    out[((size_t)b*HW + h)*HW + w] = 1.f / (1.f + expf(-t));
}

// ===========================================================================
// launch
// ===========================================================================
extern "C" void kernel_launch(void* const* d_in, const int* in_sizes, int n_in,
                              void* d_out, int out_size)
{
    const float* x      = (const float*)d_in[0];
    const float* c1w    = (const float*)d_in[1];
    const float* c1b    = (const float*)d_in[2];
    const float* c2w    = (const float*)d_in[3];
    const float* c2b    = (const float*)d_in[4];
    const float* d1w    = (const float*)d_in[5];
    const float* d1b    = (const float*)d_in[6];
    const float* d2w    = (const float*)d_in[7];
    const float* d2b    = (const float*)d_in[8];
    const float* d3w    = (const float*)d_in[9];
    const float* d3b    = (const float*)d_in[10];
    const float* outw   = (const float*)d_in[11];
    const float* outb   = (const float*)d_in[12];
    float* out = (float*)d_out;

    (void)in_sizes; (void)n_in; (void)out_size;

    cudaFuncSetAttribute(conv2_kernel,
                         cudaFuncAttributeMaxDynamicSharedMemorySize, C2_SMEM_B);

    conv1_kernel<<<dim3(8, 8, BATCH), 256>>>(x, c1w, c1b);
    conv2_kernel<<<dim3(4, 4, BATCH), 512, C2_SMEM_B>>>(c2w, c2b);
    dense1_kernel<<<dim3(5, KSPLITS), 256>>>(d1w);
    dense23_kernel<<<BATCH, 128>>>(d1b, d2w, d2b, d3w, d3b);
    sampler_kernel<<<dim3(HW, BATCH), 256>>>(x, outw, outb, out);
}